// round 9
// baseline (speedup 1.0000x reference)
#include <cuda_runtime.h>
#include <cuda_bf16.h>
#include <cstdint>

// ---------------------------------------------------------------------------
// 2-layer tanh RNN, B=64, T=512, D=H0=H1=1024.
//   prep:   split weights (transposed [n][k]) and x into bf16 (hi,lo)
//   pre:    U[b,t,:] = x_t @ W0x + b0  (smem-tiled parallel GEMM)
//   rnn:    persistent 128-CTA kernel; per step:
//             GEMM0 (smem weights + staged A, ldmatrix + split-3 HMMA)
//             -> bar -> reduce0+tanh -> bar -> GEMM1 -> bar -> reduce1 -> bar
// ---------------------------------------------------------------------------

#define BB 64
#define TT 512
#define DD 1024
#define HH 1024
#define KK1 2048
#define NSPLIT 8
#define NTILES 16
#define GRIDP (NSPLIT * NTILES)   // 128 CTAs, co-resident on 148 SMs
#define BLK 256                   // 8 warps: 2 m-stripes x 4 n-groups

#define LDK0 136                  // padded k-stride (128-wide tiles): +4 banks/row
#define LDK1 264                  // padded k-stride (256-wide tiles): +4 banks/row

typedef __nv_bfloat16 bf16;

// -------------------- device scratch (allocation-free rule) ----------------
__device__ bf16 g_W0h_hi[HH * HH], g_W0h_lo[HH * HH];    // [n][k], ld=HH
__device__ bf16 g_W0x_hi[HH * DD], g_W0x_lo[HH * DD];    // [n][k], ld=DD
__device__ bf16 g_W1_hi[HH * KK1], g_W1_lo[HH * KK1];    // [n][k], ld=KK1
__device__ bf16 g_x_hi[BB * TT * DD], g_x_lo[BB * TT * DD];
__device__ float g_U[BB * TT * HH];                      // x@W0x + b0
__device__ bf16 g_A0_hi[BB * HH], g_A0_lo[BB * HH];      // h0_prev
__device__ bf16 g_A1_hi[BB * KK1], g_A1_lo[BB * KK1];    // [h1_prev | h0]
__device__ float g_Cpart[NSPLIT * BB * HH];              // split-K partials
__device__ unsigned g_bar_arrive;
__device__ volatile unsigned g_bar_gen;

// -------------------- helpers ---------------------------------------------
__device__ __forceinline__ void split2(float v, bf16& hi, bf16& lo) {
    hi = __float2bfloat16(v);
    lo = __float2bfloat16(v - __bfloat162float(hi));
}

__device__ __forceinline__ uint32_t s2u(const void* p) {
    return (uint32_t)__cvta_generic_to_shared(p);
}

__device__ __forceinline__ void mma16816(float c[4], const unsigned a[4],
                                         unsigned b0, unsigned b1) {
    asm volatile(
        "mma.sync.aligned.m16n8k16.row.col.f32.bf16.bf16.f32 "
        "{%0,%1,%2,%3}, {%4,%5,%6,%7}, {%8,%9}, {%0,%1,%2,%3};\n"
        : "+f"(c[0]), "+f"(c[1]), "+f"(c[2]), "+f"(c[3])
        : "r"(a[0]), "r"(a[1]), "r"(a[2]), "r"(a[3]), "r"(b0), "r"(b1));
}

__device__ __forceinline__ void ldsm_x4(uint32_t addr, unsigned r[4]) {
    asm volatile(
        "ldmatrix.sync.aligned.m8n8.x4.shared.b16 {%0,%1,%2,%3}, [%4];\n"
        : "=r"(r[0]), "=r"(r[1]), "=r"(r[2]), "=r"(r[3]) : "r"(addr));
}

// Coalesced gmem->smem stage of a [64 x WIDTH] bf16 tile into padded [64][LDK].
template <int WIDTH, int LDK>
__device__ __forceinline__ void stage(const bf16* __restrict__ g, int gld,
                                      bf16* __restrict__ s) {
    constexpr int CH = WIDTH / 8;  // uint4 chunks per row
#pragma unroll
    for (int idx = threadIdx.x; idx < 64 * CH; idx += BLK) {
        int r = idx / CH, c = idx % CH;
        *reinterpret_cast<uint4*>(s + r * LDK + c * 8) =
            *reinterpret_cast<const uint4*>(g + r * gld + c * 8);
    }
}

// 64x64 output tile from smem operands. 8 warps: warp tile m32 x n16.
// A [64][LDK] row-major (hi,lo), W^T [64 n][LDK k] (hi,lo). Split-3 products.
template <int LDK>
__device__ __forceinline__ void gemm_smem(uint32_t sa_hi, uint32_t sa_lo,
                                          uint32_t sw_hi, uint32_t sw_lo,
                                          int klen, float (&acc)[2][2][4]) {
    const int lane = threadIdx.x & 31;
    const int w = threadIdx.x >> 5;
    const int wm = (w & 1) * 32;
    const int wn = (w >> 1) * 16;
    const int quad = lane >> 3, i8 = lane & 7;

    // ldmatrix.x4 lane address bases (per the m16n8k16 fragment layouts)
    const int a_row = wm + (quad & 1) * 8 + i8;
    const int a_ko = (quad >> 1) * 8;
    uint32_t uAh = sa_hi + (a_row * LDK + a_ko) * 2;
    uint32_t uAl = sa_lo + (a_row * LDK + a_ko) * 2;
    const int b_row = wn + (quad >> 1) * 8 + i8;
    const int b_ko = (quad & 1) * 8;
    uint32_t uBh = sw_hi + (b_row * LDK + b_ko) * 2;
    uint32_t uBl = sw_lo + (b_row * LDK + b_ko) * 2;

    for (int k = 0; k < klen; k += 16) {
        unsigned ah0[4], ah1[4], al0[4], al1[4], bh[4], bl[4];
        ldsm_x4(uAh + 2 * k, ah0);
        ldsm_x4(uAh + 2 * k + 16 * LDK * 2, ah1);
        ldsm_x4(uAl + 2 * k, al0);
        ldsm_x4(uAl + 2 * k + 16 * LDK * 2, al1);
        ldsm_x4(uBh + 2 * k, bh);
        ldsm_x4(uBl + 2 * k, bl);
#pragma unroll
        for (int mi = 0; mi < 2; mi++) {
            const unsigned* ah = mi ? ah1 : ah0;
            const unsigned* al = mi ? al1 : al0;
#pragma unroll
            for (int nj = 0; nj < 2; nj++) {
                mma16816(acc[mi][nj], ah, bh[2 * nj], bh[2 * nj + 1]);
                mma16816(acc[mi][nj], ah, bl[2 * nj], bl[2 * nj + 1]);
                mma16816(acc[mi][nj], al, bh[2 * nj], bh[2 * nj + 1]);
            }
        }
    }
}

__device__ __forceinline__ void zero_acc(float (&acc)[2][2][4]) {
#pragma unroll
    for (int i = 0; i < 2; i++)
#pragma unroll
        for (int j = 0; j < 2; j++)
#pragma unroll
            for (int q = 0; q < 4; q++) acc[i][j][q] = 0.0f;
}

__device__ __forceinline__ void store_part(const float (&acc)[2][2][4],
                                           int ks, int n0) {
    const int lane = threadIdx.x & 31, w = threadIdx.x >> 5;
    const int wm = (w & 1) * 32, wn = (w >> 1) * 16;
    const int gr = lane >> 2, tc = lane & 3;
    float* base = g_Cpart + ks * (BB * HH);
#pragma unroll
    for (int mi = 0; mi < 2; mi++)
#pragma unroll
        for (int nj = 0; nj < 2; nj++) {
            int r = wm + mi * 16 + gr;
            int c = n0 + wn + nj * 8 + tc * 2;
            *reinterpret_cast<float2*>(&base[r * HH + c]) =
                make_float2(acc[mi][nj][0], acc[mi][nj][1]);
            *reinterpret_cast<float2*>(&base[(r + 8) * HH + c]) =
                make_float2(acc[mi][nj][2], acc[mi][nj][3]);
        }
}

// grid barrier: release fence + arrive; last CTA bumps generation.
__device__ __forceinline__ void grid_barrier(unsigned& lgen) {
    __syncthreads();
    if (threadIdx.x == 0) {
        __threadfence();
        unsigned prev = atomicAdd(&g_bar_arrive, 1u);
        if (prev == GRIDP - 1) {
            g_bar_arrive = 0;
            __threadfence();
            g_bar_gen = lgen + 1;
        } else {
            while (g_bar_gen <= lgen) { }
        }
        lgen++;
        __threadfence();
    }
    __syncthreads();
}

// -------------------- kernel 1: prep (split + transpose) ------------------
__global__ void prep_kernel(const float* __restrict__ x,
                            const float* __restrict__ W0,
                            const float* __restrict__ W1) {
    int tid = blockIdx.x * blockDim.x + threadIdx.x;
    int stride = gridDim.x * blockDim.x;
    if (tid == 0) { g_bar_arrive = 0; g_bar_gen = 0; }

    for (int i = tid; i < BB * TT * DD; i += stride)
        split2(x[i], g_x_hi[i], g_x_lo[i]);
    for (int i = tid; i < HH * HH; i += stride) {
        int n = i >> 10, k = i & 1023;
        split2(W0[k * HH + n], g_W0h_hi[i], g_W0h_lo[i]);
    }
    for (int i = tid; i < HH * DD; i += stride) {
        int n = i >> 10, k = i & 1023;
        split2(W0[(HH + k) * HH + n], g_W0x_hi[i], g_W0x_lo[i]);
    }
    for (int i = tid; i < HH * KK1; i += stride) {
        int n = i >> 11, k = i & 2047;
        split2(W1[k * HH + n], g_W1_hi[i], g_W1_lo[i]);
    }
    bf16 z = __float2bfloat16(0.0f);
    for (int i = tid; i < BB * HH; i += stride) { g_A0_hi[i] = z; g_A0_lo[i] = z; }
    for (int i = tid; i < BB * KK1; i += stride) { g_A1_hi[i] = z; g_A1_lo[i] = z; }
}

// -------------------- kernel 2: U = x @ W0x + b0 ---------------------------
// 8192 CTAs; 16 consecutive bids share one m-tile so x stays L2-hot.
#define PRE_SMEM (4 * 64 * LDK0 * 2)
__global__ void __launch_bounds__(BLK) precompute_kernel(const float* __restrict__ b0) {
    extern __shared__ bf16 sm[];
    bf16* sA_hi = sm;
    bf16* sA_lo = sA_hi + 64 * LDK0;
    bf16* sW_hi = sA_lo + 64 * LDK0;
    bf16* sW_lo = sW_hi + 64 * LDK0;

    const int mtile = blockIdx.x >> 4;    // 512 m-tiles of 64 rows (b*T+t flat)
    const int ntile = blockIdx.x & 15;    // 16 n-tiles of 64 cols
    const int row0 = mtile * 64, n0 = ntile * 64;

    uint32_t uA_hi = s2u(sA_hi), uA_lo = s2u(sA_lo);
    uint32_t uW_hi = s2u(sW_hi), uW_lo = s2u(sW_lo);

    float acc[2][2][4];
    zero_acc(acc);

    for (int kc = 0; kc < 8; kc++) {
        if (kc) __syncthreads();
        stage<128, LDK0>(g_x_hi + row0 * DD + kc * 128, DD, sA_hi);
        stage<128, LDK0>(g_x_lo + row0 * DD + kc * 128, DD, sA_lo);
        stage<128, LDK0>(g_W0x_hi + n0 * DD + kc * 128, DD, sW_hi);
        stage<128, LDK0>(g_W0x_lo + n0 * DD + kc * 128, DD, sW_lo);
        __syncthreads();
        gemm_smem<LDK0>(uA_hi, uA_lo, uW_hi, uW_lo, 128, acc);
    }

    const int lane = threadIdx.x & 31, w = threadIdx.x >> 5;
    const int wm = (w & 1) * 32, wn = (w >> 1) * 16;
    const int gr = lane >> 2, tc = lane & 3;
#pragma unroll
    for (int mi = 0; mi < 2; mi++)
#pragma unroll
        for (int nj = 0; nj < 2; nj++) {
            int r = row0 + wm + mi * 16 + gr;
            int c = n0 + wn + nj * 8 + tc * 2;
            float bA = b0[c], bBv = b0[c + 1];
            g_U[r * HH + c]           = acc[mi][nj][0] + bA;
            g_U[r * HH + c + 1]       = acc[mi][nj][1] + bBv;
            g_U[(r + 8) * HH + c]     = acc[mi][nj][2] + bA;
            g_U[(r + 8) * HH + c + 1] = acc[mi][nj][3] + bBv;
        }
}

// -------------------- kernel 3: persistent recurrence ----------------------
// smem: W0h slice [64][LDK0] hi/lo + W1 slice [64][LDK1] hi/lo + A [64][LDK1] hi/lo
#define RNN_SMEM ((2 * 64 * LDK0 + 4 * 64 * LDK1) * 2)
__global__ void __launch_bounds__(BLK) rnn_kernel(const float* __restrict__ b1,
                                                  float* __restrict__ out) {
    extern __shared__ bf16 sm[];
    bf16* sW0_hi = sm;
    bf16* sW0_lo = sW0_hi + 64 * LDK0;
    bf16* sW1_hi = sW0_lo + 64 * LDK0;
    bf16* sW1_lo = sW1_hi + 64 * LDK1;
    bf16* sA_hi  = sW1_lo + 64 * LDK1;
    bf16* sA_lo  = sA_hi + 64 * LDK1;

    const int bid = blockIdx.x;
    const int ntile = bid & 15;      // 16 n-tiles of 64
    const int ks = bid >> 4;         // 8 k-splits
    const int n0 = ntile * 64;
    const int gtid = bid * BLK + threadIdx.x;

    // Preload this CTA's weight slices into smem ONCE (persist across t-loop;
    // smem is untouched by the barrier's L1 invalidations).
    stage<128, LDK0>(g_W0h_hi + n0 * HH + ks * 128, HH, sW0_hi);
    stage<128, LDK0>(g_W0h_lo + n0 * HH + ks * 128, HH, sW0_lo);
    stage<256, LDK1>(g_W1_hi + n0 * KK1 + ks * 256, KK1, sW1_hi);
    stage<256, LDK1>(g_W1_lo + n0 * KK1 + ks * 256, KK1, sW1_lo);

    uint32_t uW0_hi = s2u(sW0_hi), uW0_lo = s2u(sW0_lo);
    uint32_t uW1_hi = s2u(sW1_hi), uW1_lo = s2u(sW1_lo);
    uint32_t uA_hi = s2u(sA_hi), uA_lo = s2u(sA_lo);

    unsigned lgen = 0;
    if (threadIdx.x == 0) lgen = g_bar_gen;
    __syncthreads();

    for (int t = 0; t < TT; t++) {
        // ---- layer 0 GEMM: h0_prev @ W0h, K split 8 x 128 ----
        stage<128, LDK0>(g_A0_hi + ks * 128, HH, sA_hi);
        stage<128, LDK0>(g_A0_lo + ks * 128, HH, sA_lo);
        __syncthreads();
        {
            float acc[2][2][4];
            zero_acc(acc);
            gemm_smem<LDK0>(uA_hi, uA_lo, uW0_hi, uW0_lo, 128, acc);
            store_part(acc, ks, n0);
        }
        grid_barrier(lgen);

        // ---- reduce0 + tanh -> h0 (exactly one float2 per thread) ----
        {
            int idx = gtid;  // BB*HH/2 == GRIDP*BLK
            int e = idx * 2;
            int m = e >> 10, n = e & 1023;
            float2 u = *reinterpret_cast<const float2*>(&g_U[(m * TT + t) * HH + n]);
            float s0 = u.x, s1 = u.y;
#pragma unroll
            for (int p = 0; p < NSPLIT; p++) {
                float2 v = *reinterpret_cast<const float2*>(&g_Cpart[p * (BB * HH) + e]);
                s0 += v.x; s1 += v.y;
            }
            float h0a = tanhf(s0), h0b = tanhf(s1);
            __nv_bfloat162 hh, ll;
            split2(h0a, hh.x, ll.x);
            split2(h0b, hh.y, ll.y);
            *reinterpret_cast<__nv_bfloat162*>(&g_A1_hi[m * KK1 + HH + n]) = hh;
            *reinterpret_cast<__nv_bfloat162*>(&g_A1_lo[m * KK1 + HH + n]) = ll;
            *reinterpret_cast<__nv_bfloat162*>(&g_A0_hi[e]) = hh;
            *reinterpret_cast<__nv_bfloat162*>(&g_A0_lo[e]) = ll;
            if (t == TT - 1) {
                out[BB * TT * HH + m * (2 * HH) + n]     = h0a;  // h0_f
                out[BB * TT * HH + m * (2 * HH) + n + 1] = h0b;
            }
        }
        grid_barrier(lgen);

        // ---- layer 1 GEMM: [h1_prev | h0] @ W1, K split 8 x 256 ----
        stage<256, LDK1>(g_A1_hi + ks * 256, KK1, sA_hi);
        stage<256, LDK1>(g_A1_lo + ks * 256, KK1, sA_lo);
        __syncthreads();
        {
            float acc[2][2][4];
            zero_acc(acc);
            gemm_smem<LDK1>(uA_hi, uA_lo, uW1_hi, uW1_lo, 256, acc);
            store_part(acc, ks, n0);
        }
        grid_barrier(lgen);

        // ---- reduce1 + tanh -> h1; write outputs ----
        {
            int idx = gtid;
            int e = idx * 2;
            int m = e >> 10, n = e & 1023;
            float s0 = b1[n], s1 = b1[n + 1];
#pragma unroll
            for (int p = 0; p < NSPLIT; p++) {
                float2 v = *reinterpret_cast<const float2*>(&g_Cpart[p * (BB * HH) + e]);
                s0 += v.x; s1 += v.y;
            }
            float h1a = tanhf(s0), h1b = tanhf(s1);
            __nv_bfloat162 hh, ll;
            split2(h1a, hh.x, ll.x);
            split2(h1b, hh.y, ll.y);
            *reinterpret_cast<__nv_bfloat162*>(&g_A1_hi[m * KK1 + n]) = hh;
            *reinterpret_cast<__nv_bfloat162*>(&g_A1_lo[m * KK1 + n]) = ll;
            *reinterpret_cast<float2*>(&out[(m * TT + t) * HH + n]) =
                make_float2(h1a, h1b);
            if (t == TT - 1) {
                out[BB * TT * HH + m * (2 * HH) + HH + n]     = h1a;  // h1_f
                out[BB * TT * HH + m * (2 * HH) + HH + n + 1] = h1b;
            }
        }
        grid_barrier(lgen);
    }
}

// -------------------- launch ----------------------------------------------
extern "C" void kernel_launch(void* const* d_in, const int* in_sizes, int n_in,
                              void* d_out, int out_size) {
    const float* x = nullptr;
    const float* W[2] = {nullptr, nullptr};
    const float* bv[2] = {nullptr, nullptr};
    int nw = 0, nb = 0;
    for (int i = 0; i < n_in; i++) {
        if (in_sizes[i] == BB * TT * DD) x = (const float*)d_in[i];
        else if (in_sizes[i] == KK1 * HH) { if (nw < 2) W[nw++] = (const float*)d_in[i]; }
        else if (in_sizes[i] == HH)       { if (nb < 2) bv[nb++] = (const float*)d_in[i]; }
    }
    const float* W0 = W[0];
    const float* W1 = W[1];
    const float* b0 = bv[0];
    const float* b1 = bv[1];
    float* out = (float*)d_out;

    cudaFuncSetAttribute(precompute_kernel,
                         cudaFuncAttributeMaxDynamicSharedMemorySize, PRE_SMEM);
    cudaFuncSetAttribute(rnn_kernel,
                         cudaFuncAttributeMaxDynamicSharedMemorySize, RNN_SMEM);

    prep_kernel<<<2048, 256>>>(x, W0, W1);
    precompute_kernel<<<512 * 16, BLK, PRE_SMEM>>>(b0);
    rnn_kernel<<<GRIDP, BLK, RNN_SMEM>>>(b1, out);
}

// round 10
// speedup vs baseline: 1.0081x; 1.0081x over previous
#include <cuda_runtime.h>
#include <cuda_bf16.h>
#include <cstdint>

// ---------------------------------------------------------------------------
// 2-layer tanh RNN, B=64, T=512, D=H0=H1=1024.
//   prep:   split weights (transposed [n][k]) and x into bf16 (hi,lo)
//   pre:    U[b,t,:] = x_t @ W0x + b0  (smem-tiled parallel GEMM)
//   rnn:    persistent 128-CTA kernel; per step:
//             GEMM0 (smem weights + staged A, ldmatrix + split-3 HMMA)
//             -> bar -> reduce0+tanh -> bar -> GEMM1 -> bar -> reduce1 -> bar
// ---------------------------------------------------------------------------

#define BB 64
#define TT 512
#define DD 1024
#define HH 1024
#define KK1 2048
#define NSPLIT 8
#define NTILES 16
#define GRIDP (NSPLIT * NTILES)   // 128 CTAs, co-resident on 148 SMs
#define BLK 256                   // 8 warps: 2 m-stripes x 4 n-groups

#define LDK0 136                  // padded k-stride (128-wide tiles): +4 banks/row
#define LDK1 264                  // padded k-stride (256-wide tiles): +4 banks/row

typedef __nv_bfloat16 bf16;

// -------------------- device scratch (allocation-free rule) ----------------
__device__ bf16 g_W0h_hi[HH * HH], g_W0h_lo[HH * HH];    // [n][k], ld=HH
__device__ bf16 g_W0x_hi[HH * DD], g_W0x_lo[HH * DD];    // [n][k], ld=DD
__device__ bf16 g_W1_hi[HH * KK1], g_W1_lo[HH * KK1];    // [n][k], ld=KK1
__device__ bf16 g_x_hi[BB * TT * DD], g_x_lo[BB * TT * DD];
__device__ float g_U[BB * TT * HH];                      // x@W0x + b0
__device__ bf16 g_A0_hi[BB * HH], g_A0_lo[BB * HH];      // h0_prev
__device__ bf16 g_A1_hi[BB * KK1], g_A1_lo[BB * KK1];    // [h1_prev | h0]
__device__ float g_Cpart[NSPLIT * BB * HH];              // split-K partials
__device__ unsigned g_bar_arrive;
__device__ volatile unsigned g_bar_gen;

// -------------------- helpers ---------------------------------------------
__device__ __forceinline__ void split2(float v, bf16& hi, bf16& lo) {
    hi = __float2bfloat16(v);
    lo = __float2bfloat16(v - __bfloat162float(hi));
}

__device__ __forceinline__ uint32_t s2u(const void* p) {
    return (uint32_t)__cvta_generic_to_shared(p);
}

__device__ __forceinline__ void mma16816(float c[4], const unsigned a[4],
                                         unsigned b0, unsigned b1) {
    asm volatile(
        "mma.sync.aligned.m16n8k16.row.col.f32.bf16.bf16.f32 "
        "{%0,%1,%2,%3}, {%4,%5,%6,%7}, {%8,%9}, {%0,%1,%2,%3};\n"
        : "+f"(c[0]), "+f"(c[1]), "+f"(c[2]), "+f"(c[3])
        : "r"(a[0]), "r"(a[1]), "r"(a[2]), "r"(a[3]), "r"(b0), "r"(b1));
}

__device__ __forceinline__ void ldsm_x4(uint32_t addr, unsigned r[4]) {
    asm volatile(
        "ldmatrix.sync.aligned.m8n8.x4.shared.b16 {%0,%1,%2,%3}, [%4];\n"
        : "=r"(r[0]), "=r"(r[1]), "=r"(r[2]), "=r"(r[3]) : "r"(addr));
}

// Coalesced gmem->smem stage of a [64 x WIDTH] bf16 tile into padded [64][LDK].
template <int WIDTH, int LDK>
__device__ __forceinline__ void stage(const bf16* __restrict__ g, int gld,
                                      bf16* __restrict__ s) {
    constexpr int CH = WIDTH / 8;  // uint4 chunks per row
#pragma unroll
    for (int idx = threadIdx.x; idx < 64 * CH; idx += BLK) {
        int r = idx / CH, c = idx % CH;
        *reinterpret_cast<uint4*>(s + r * LDK + c * 8) =
            *reinterpret_cast<const uint4*>(g + r * gld + c * 8);
    }
}

// 64x64 output tile from smem operands. 8 warps: warp tile m32 x n16.
// A [64][LDK] row-major (hi,lo), W^T [64 n][LDK k] (hi,lo). Split-3 products.
template <int LDK>
__device__ __forceinline__ void gemm_smem(uint32_t sa_hi, uint32_t sa_lo,
                                          uint32_t sw_hi, uint32_t sw_lo,
                                          int klen, float (&acc)[2][2][4]) {
    const int lane = threadIdx.x & 31;
    const int w = threadIdx.x >> 5;
    const int wm = (w & 1) * 32;
    const int wn = (w >> 1) * 16;
    const int quad = lane >> 3, i8 = lane & 7;

    // ldmatrix.x4 lane address bases (per the m16n8k16 fragment layouts)
    const int a_row = wm + (quad & 1) * 8 + i8;
    const int a_ko = (quad >> 1) * 8;
    uint32_t uAh = sa_hi + (a_row * LDK + a_ko) * 2;
    uint32_t uAl = sa_lo + (a_row * LDK + a_ko) * 2;
    const int b_row = wn + (quad >> 1) * 8 + i8;
    const int b_ko = (quad & 1) * 8;
    uint32_t uBh = sw_hi + (b_row * LDK + b_ko) * 2;
    uint32_t uBl = sw_lo + (b_row * LDK + b_ko) * 2;

    for (int k = 0; k < klen; k += 16) {
        unsigned ah0[4], ah1[4], al0[4], al1[4], bh[4], bl[4];
        ldsm_x4(uAh + 2 * k, ah0);
        ldsm_x4(uAh + 2 * k + 16 * LDK * 2, ah1);
        ldsm_x4(uAl + 2 * k, al0);
        ldsm_x4(uAl + 2 * k + 16 * LDK * 2, al1);
        ldsm_x4(uBh + 2 * k, bh);
        ldsm_x4(uBl + 2 * k, bl);
#pragma unroll
        for (int mi = 0; mi < 2; mi++) {
            const unsigned* ah = mi ? ah1 : ah0;
            const unsigned* al = mi ? al1 : al0;
#pragma unroll
            for (int nj = 0; nj < 2; nj++) {
                mma16816(acc[mi][nj], ah, bh[2 * nj], bh[2 * nj + 1]);
                mma16816(acc[mi][nj], ah, bl[2 * nj], bl[2 * nj + 1]);
                mma16816(acc[mi][nj], al, bh[2 * nj], bh[2 * nj + 1]);
            }
        }
    }
}

__device__ __forceinline__ void zero_acc(float (&acc)[2][2][4]) {
#pragma unroll
    for (int i = 0; i < 2; i++)
#pragma unroll
        for (int j = 0; j < 2; j++)
#pragma unroll
            for (int q = 0; q < 4; q++) acc[i][j][q] = 0.0f;
}

__device__ __forceinline__ void store_part(const float (&acc)[2][2][4],
                                           int ks, int n0) {
    const int lane = threadIdx.x & 31, w = threadIdx.x >> 5;
    const int wm = (w & 1) * 32, wn = (w >> 1) * 16;
    const int gr = lane >> 2, tc = lane & 3;
    float* base = g_Cpart + ks * (BB * HH);
#pragma unroll
    for (int mi = 0; mi < 2; mi++)
#pragma unroll
        for (int nj = 0; nj < 2; nj++) {
            int r = wm + mi * 16 + gr;
            int c = n0 + wn + nj * 8 + tc * 2;
            *reinterpret_cast<float2*>(&base[r * HH + c]) =
                make_float2(acc[mi][nj][0], acc[mi][nj][1]);
            *reinterpret_cast<float2*>(&base[(r + 8) * HH + c]) =
                make_float2(acc[mi][nj][2], acc[mi][nj][3]);
        }
}

// grid barrier: release fence + arrive; last CTA bumps generation.
__device__ __forceinline__ void grid_barrier(unsigned& lgen) {
    __syncthreads();
    if (threadIdx.x == 0) {
        __threadfence();
        unsigned prev = atomicAdd(&g_bar_arrive, 1u);
        if (prev == GRIDP - 1) {
            g_bar_arrive = 0;
            __threadfence();
            g_bar_gen = lgen + 1;
        } else {
            while (g_bar_gen <= lgen) { }
        }
        lgen++;
        __threadfence();
    }
    __syncthreads();
}

// -------------------- kernel 1: prep (split + transpose) ------------------
__global__ void prep_kernel(const float* __restrict__ x,
                            const float* __restrict__ W0,
                            const float* __restrict__ W1) {
    int tid = blockIdx.x * blockDim.x + threadIdx.x;
    int stride = gridDim.x * blockDim.x;
    if (tid == 0) { g_bar_arrive = 0; g_bar_gen = 0; }

    for (int i = tid; i < BB * TT * DD; i += stride)
        split2(x[i], g_x_hi[i], g_x_lo[i]);
    for (int i = tid; i < HH * HH; i += stride) {
        int n = i >> 10, k = i & 1023;
        split2(W0[k * HH + n], g_W0h_hi[i], g_W0h_lo[i]);
    }
    for (int i = tid; i < HH * DD; i += stride) {
        int n = i >> 10, k = i & 1023;
        split2(W0[(HH + k) * HH + n], g_W0x_hi[i], g_W0x_lo[i]);
    }
    for (int i = tid; i < HH * KK1; i += stride) {
        int n = i >> 11, k = i & 2047;
        split2(W1[k * HH + n], g_W1_hi[i], g_W1_lo[i]);
    }
    bf16 z = __float2bfloat16(0.0f);
    for (int i = tid; i < BB * HH; i += stride) { g_A0_hi[i] = z; g_A0_lo[i] = z; }
    for (int i = tid; i < BB * KK1; i += stride) { g_A1_hi[i] = z; g_A1_lo[i] = z; }
}

// -------------------- kernel 2: U = x @ W0x + b0 ---------------------------
// 8192 CTAs; 16 consecutive bids share one m-tile so x stays L2-hot.
#define PRE_SMEM (4 * 64 * LDK0 * 2)
__global__ void __launch_bounds__(BLK) precompute_kernel(const float* __restrict__ b0) {
    extern __shared__ bf16 sm[];
    bf16* sA_hi = sm;
    bf16* sA_lo = sA_hi + 64 * LDK0;
    bf16* sW_hi = sA_lo + 64 * LDK0;
    bf16* sW_lo = sW_hi + 64 * LDK0;

    const int mtile = blockIdx.x >> 4;    // 512 m-tiles of 64 rows (b*T+t flat)
    const int ntile = blockIdx.x & 15;    // 16 n-tiles of 64 cols
    const int row0 = mtile * 64, n0 = ntile * 64;

    uint32_t uA_hi = s2u(sA_hi), uA_lo = s2u(sA_lo);
    uint32_t uW_hi = s2u(sW_hi), uW_lo = s2u(sW_lo);

    float acc[2][2][4];
    zero_acc(acc);

    for (int kc = 0; kc < 8; kc++) {
        if (kc) __syncthreads();
        stage<128, LDK0>(g_x_hi + row0 * DD + kc * 128, DD, sA_hi);
        stage<128, LDK0>(g_x_lo + row0 * DD + kc * 128, DD, sA_lo);
        stage<128, LDK0>(g_W0x_hi + n0 * DD + kc * 128, DD, sW_hi);
        stage<128, LDK0>(g_W0x_lo + n0 * DD + kc * 128, DD, sW_lo);
        __syncthreads();
        gemm_smem<LDK0>(uA_hi, uA_lo, uW_hi, uW_lo, 128, acc);
    }

    const int lane = threadIdx.x & 31, w = threadIdx.x >> 5;
    const int wm = (w & 1) * 32, wn = (w >> 1) * 16;
    const int gr = lane >> 2, tc = lane & 3;
#pragma unroll
    for (int mi = 0; mi < 2; mi++)
#pragma unroll
        for (int nj = 0; nj < 2; nj++) {
            int r = row0 + wm + mi * 16 + gr;
            int c = n0 + wn + nj * 8 + tc * 2;
            float bA = b0[c], bBv = b0[c + 1];
            g_U[r * HH + c]           = acc[mi][nj][0] + bA;
            g_U[r * HH + c + 1]       = acc[mi][nj][1] + bBv;
            g_U[(r + 8) * HH + c]     = acc[mi][nj][2] + bA;
            g_U[(r + 8) * HH + c + 1] = acc[mi][nj][3] + bBv;
        }
}

// -------------------- kernel 3: persistent recurrence ----------------------
// smem: W0h slice [64][LDK0] hi/lo + W1 slice [64][LDK1] hi/lo + A [64][LDK1] hi/lo
#define RNN_SMEM ((2 * 64 * LDK0 + 4 * 64 * LDK1) * 2)
__global__ void __launch_bounds__(BLK) rnn_kernel(const float* __restrict__ b1,
                                                  float* __restrict__ out) {
    extern __shared__ bf16 sm[];
    bf16* sW0_hi = sm;
    bf16* sW0_lo = sW0_hi + 64 * LDK0;
    bf16* sW1_hi = sW0_lo + 64 * LDK0;
    bf16* sW1_lo = sW1_hi + 64 * LDK1;
    bf16* sA_hi  = sW1_lo + 64 * LDK1;
    bf16* sA_lo  = sA_hi + 64 * LDK1;

    const int bid = blockIdx.x;
    const int ntile = bid & 15;      // 16 n-tiles of 64
    const int ks = bid >> 4;         // 8 k-splits
    const int n0 = ntile * 64;
    const int gtid = bid * BLK + threadIdx.x;

    // Preload this CTA's weight slices into smem ONCE (persist across t-loop;
    // smem is untouched by the barrier's L1 invalidations).
    stage<128, LDK0>(g_W0h_hi + n0 * HH + ks * 128, HH, sW0_hi);
    stage<128, LDK0>(g_W0h_lo + n0 * HH + ks * 128, HH, sW0_lo);
    stage<256, LDK1>(g_W1_hi + n0 * KK1 + ks * 256, KK1, sW1_hi);
    stage<256, LDK1>(g_W1_lo + n0 * KK1 + ks * 256, KK1, sW1_lo);

    uint32_t uW0_hi = s2u(sW0_hi), uW0_lo = s2u(sW0_lo);
    uint32_t uW1_hi = s2u(sW1_hi), uW1_lo = s2u(sW1_lo);
    uint32_t uA_hi = s2u(sA_hi), uA_lo = s2u(sA_lo);

    unsigned lgen = 0;
    if (threadIdx.x == 0) lgen = g_bar_gen;
    __syncthreads();

    for (int t = 0; t < TT; t++) {
        // ---- layer 0 GEMM: h0_prev @ W0h, K split 8 x 128 ----
        stage<128, LDK0>(g_A0_hi + ks * 128, HH, sA_hi);
        stage<128, LDK0>(g_A0_lo + ks * 128, HH, sA_lo);
        __syncthreads();
        {
            float acc[2][2][4];
            zero_acc(acc);
            gemm_smem<LDK0>(uA_hi, uA_lo, uW0_hi, uW0_lo, 128, acc);
            store_part(acc, ks, n0);
        }
        grid_barrier(lgen);

        // ---- reduce0 + tanh -> h0 (exactly one float2 per thread) ----
        {
            int idx = gtid;  // BB*HH/2 == GRIDP*BLK
            int e = idx * 2;
            int m = e >> 10, n = e & 1023;
            float2 u = *reinterpret_cast<const float2*>(&g_U[(m * TT + t) * HH + n]);
            float s0 = u.x, s1 = u.y;
#pragma unroll
            for (int p = 0; p < NSPLIT; p++) {
                float2 v = *reinterpret_cast<const float2*>(&g_Cpart[p * (BB * HH) + e]);
                s0 += v.x; s1 += v.y;
            }
            float h0a = tanhf(s0), h0b = tanhf(s1);
            __nv_bfloat162 hh, ll;
            split2(h0a, hh.x, ll.x);
            split2(h0b, hh.y, ll.y);
            *reinterpret_cast<__nv_bfloat162*>(&g_A1_hi[m * KK1 + HH + n]) = hh;
            *reinterpret_cast<__nv_bfloat162*>(&g_A1_lo[m * KK1 + HH + n]) = ll;
            *reinterpret_cast<__nv_bfloat162*>(&g_A0_hi[e]) = hh;
            *reinterpret_cast<__nv_bfloat162*>(&g_A0_lo[e]) = ll;
            if (t == TT - 1) {
                out[BB * TT * HH + m * (2 * HH) + n]     = h0a;  // h0_f
                out[BB * TT * HH + m * (2 * HH) + n + 1] = h0b;
            }
        }
        grid_barrier(lgen);

        // ---- layer 1 GEMM: [h1_prev | h0] @ W1, K split 8 x 256 ----
        stage<256, LDK1>(g_A1_hi + ks * 256, KK1, sA_hi);
        stage<256, LDK1>(g_A1_lo + ks * 256, KK1, sA_lo);
        __syncthreads();
        {
            float acc[2][2][4];
            zero_acc(acc);
            gemm_smem<LDK1>(uA_hi, uA_lo, uW1_hi, uW1_lo, 256, acc);
            store_part(acc, ks, n0);
        }
        grid_barrier(lgen);

        // ---- reduce1 + tanh -> h1; write outputs ----
        {
            int idx = gtid;
            int e = idx * 2;
            int m = e >> 10, n = e & 1023;
            float s0 = b1[n], s1 = b1[n + 1];
#pragma unroll
            for (int p = 0; p < NSPLIT; p++) {
                float2 v = *reinterpret_cast<const float2*>(&g_Cpart[p * (BB * HH) + e]);
                s0 += v.x; s1 += v.y;
            }
            float h1a = tanhf(s0), h1b = tanhf(s1);
            __nv_bfloat162 hh, ll;
            split2(h1a, hh.x, ll.x);
            split2(h1b, hh.y, ll.y);
            *reinterpret_cast<__nv_bfloat162*>(&g_A1_hi[m * KK1 + n]) = hh;
            *reinterpret_cast<__nv_bfloat162*>(&g_A1_lo[m * KK1 + n]) = ll;
            *reinterpret_cast<float2*>(&out[(m * TT + t) * HH + n]) =
                make_float2(h1a, h1b);
            if (t == TT - 1) {
                out[BB * TT * HH + m * (2 * HH) + HH + n]     = h1a;  // h1_f
                out[BB * TT * HH + m * (2 * HH) + HH + n + 1] = h1b;
            }
        }
        grid_barrier(lgen);
    }
}

// -------------------- launch ----------------------------------------------
extern "C" void kernel_launch(void* const* d_in, const int* in_sizes, int n_in,
                              void* d_out, int out_size) {
    const float* x = nullptr;
    const float* W[2] = {nullptr, nullptr};
    const float* bv[2] = {nullptr, nullptr};
    int nw = 0, nb = 0;
    for (int i = 0; i < n_in; i++) {
        if (in_sizes[i] == BB * TT * DD) x = (const float*)d_in[i];
        else if (in_sizes[i] == KK1 * HH) { if (nw < 2) W[nw++] = (const float*)d_in[i]; }
        else if (in_sizes[i] == HH)       { if (nb < 2) bv[nb++] = (const float*)d_in[i]; }
    }
    const float* W0 = W[0];
    const float* W1 = W[1];
    const float* b0 = bv[0];
    const float* b1 = bv[1];
    float* out = (float*)d_out;

    cudaFuncSetAttribute(precompute_kernel,
                         cudaFuncAttributeMaxDynamicSharedMemorySize, PRE_SMEM);
    cudaFuncSetAttribute(rnn_kernel,
                         cudaFuncAttributeMaxDynamicSharedMemorySize, RNN_SMEM);

    prep_kernel<<<2048, 256>>>(x, W0, W1);
    precompute_kernel<<<512 * 16, BLK, PRE_SMEM>>>(b0);
    rnn_kernel<<<GRIDP, BLK, RNN_SMEM>>>(b1, out);
}

// round 11
// speedup vs baseline: 1.0149x; 1.0067x over previous
#include <cuda_runtime.h>
#include <cuda_bf16.h>
#include <cstdint>

// ---------------------------------------------------------------------------
// 2-layer tanh RNN, B=64, T=512, D=H0=H1=1024.
//   prep:   split weights (transposed [n][k]) and x into bf16 (hi,lo)
//   pre:    U[b,t,:] = x_t @ W0x + b0  (smem-tiled parallel GEMM)
//   rnn:    persistent 128-CTA kernel; per step:
//             GEMM0 (smem weights + staged A, ldmatrix + split-3 HMMA)
//             -> bar -> reduce0+tanh -> bar -> GEMM1 -> bar -> reduce1 -> bar
// ---------------------------------------------------------------------------

#define BB 64
#define TT 512
#define DD 1024
#define HH 1024
#define KK1 2048
#define NSPLIT 8
#define NTILES 16
#define GRIDP (NSPLIT * NTILES)   // 128 CTAs, co-resident on 148 SMs
#define BLK 256                   // 8 warps: 2 m-stripes x 4 n-groups

#define LDK0 136                  // padded k-stride (128-wide tiles): +4 banks/row
#define LDK1 264                  // padded k-stride (256-wide tiles): +4 banks/row

typedef __nv_bfloat16 bf16;

// -------------------- device scratch (allocation-free rule) ----------------
__device__ bf16 g_W0h_hi[HH * HH], g_W0h_lo[HH * HH];    // [n][k], ld=HH
__device__ bf16 g_W0x_hi[HH * DD], g_W0x_lo[HH * DD];    // [n][k], ld=DD
__device__ bf16 g_W1_hi[HH * KK1], g_W1_lo[HH * KK1];    // [n][k], ld=KK1
__device__ bf16 g_x_hi[BB * TT * DD], g_x_lo[BB * TT * DD];
__device__ float g_U[BB * TT * HH];                      // x@W0x + b0
__device__ bf16 g_A0_hi[BB * HH], g_A0_lo[BB * HH];      // h0_prev
__device__ bf16 g_A1_hi[BB * KK1], g_A1_lo[BB * KK1];    // [h1_prev | h0]
__device__ float g_Cpart[NSPLIT * BB * HH];              // split-K partials
__device__ unsigned g_bar_arrive;
__device__ volatile unsigned g_bar_gen;

// -------------------- helpers ---------------------------------------------
__device__ __forceinline__ void split2(float v, bf16& hi, bf16& lo) {
    hi = __float2bfloat16(v);
    lo = __float2bfloat16(v - __bfloat162float(hi));
}

__device__ __forceinline__ uint32_t s2u(const void* p) {
    return (uint32_t)__cvta_generic_to_shared(p);
}

__device__ __forceinline__ void mma16816(float c[4], const unsigned a[4],
                                         unsigned b0, unsigned b1) {
    asm volatile(
        "mma.sync.aligned.m16n8k16.row.col.f32.bf16.bf16.f32 "
        "{%0,%1,%2,%3}, {%4,%5,%6,%7}, {%8,%9}, {%0,%1,%2,%3};\n"
        : "+f"(c[0]), "+f"(c[1]), "+f"(c[2]), "+f"(c[3])
        : "r"(a[0]), "r"(a[1]), "r"(a[2]), "r"(a[3]), "r"(b0), "r"(b1));
}

__device__ __forceinline__ void ldsm_x4(uint32_t addr, unsigned r[4]) {
    asm volatile(
        "ldmatrix.sync.aligned.m8n8.x4.shared.b16 {%0,%1,%2,%3}, [%4];\n"
        : "=r"(r[0]), "=r"(r[1]), "=r"(r[2]), "=r"(r[3]) : "r"(addr));
}

// Coalesced gmem->smem stage of a [64 x WIDTH] bf16 tile into padded [64][LDK].
template <int WIDTH, int LDK>
__device__ __forceinline__ void stage(const bf16* __restrict__ g, int gld,
                                      bf16* __restrict__ s) {
    constexpr int CH = WIDTH / 8;  // uint4 chunks per row
#pragma unroll
    for (int idx = threadIdx.x; idx < 64 * CH; idx += BLK) {
        int r = idx / CH, c = idx % CH;
        *reinterpret_cast<uint4*>(s + r * LDK + c * 8) =
            *reinterpret_cast<const uint4*>(g + r * gld + c * 8);
    }
}

// 64x64 output tile from smem operands. 8 warps: warp tile m32 x n16.
// A [64][LDK] row-major (hi,lo), W^T [64 n][LDK k] (hi,lo). Split-3 products.
template <int LDK>
__device__ __forceinline__ void gemm_smem(uint32_t sa_hi, uint32_t sa_lo,
                                          uint32_t sw_hi, uint32_t sw_lo,
                                          int klen, float (&acc)[2][2][4]) {
    const int lane = threadIdx.x & 31;
    const int w = threadIdx.x >> 5;
    const int wm = (w & 1) * 32;
    const int wn = (w >> 1) * 16;
    const int quad = lane >> 3, i8 = lane & 7;

    // ldmatrix.x4 lane address bases (per the m16n8k16 fragment layouts)
    const int a_row = wm + (quad & 1) * 8 + i8;
    const int a_ko = (quad >> 1) * 8;
    uint32_t uAh = sa_hi + (a_row * LDK + a_ko) * 2;
    uint32_t uAl = sa_lo + (a_row * LDK + a_ko) * 2;
    const int b_row = wn + (quad >> 1) * 8 + i8;
    const int b_ko = (quad & 1) * 8;
    uint32_t uBh = sw_hi + (b_row * LDK + b_ko) * 2;
    uint32_t uBl = sw_lo + (b_row * LDK + b_ko) * 2;

    for (int k = 0; k < klen; k += 16) {
        unsigned ah0[4], ah1[4], al0[4], al1[4], bh[4], bl[4];
        ldsm_x4(uAh + 2 * k, ah0);
        ldsm_x4(uAh + 2 * k + 16 * LDK * 2, ah1);
        ldsm_x4(uAl + 2 * k, al0);
        ldsm_x4(uAl + 2 * k + 16 * LDK * 2, al1);
        ldsm_x4(uBh + 2 * k, bh);
        ldsm_x4(uBl + 2 * k, bl);
#pragma unroll
        for (int mi = 0; mi < 2; mi++) {
            const unsigned* ah = mi ? ah1 : ah0;
            const unsigned* al = mi ? al1 : al0;
#pragma unroll
            for (int nj = 0; nj < 2; nj++) {
                mma16816(acc[mi][nj], ah, bh[2 * nj], bh[2 * nj + 1]);
                mma16816(acc[mi][nj], ah, bl[2 * nj], bl[2 * nj + 1]);
                mma16816(acc[mi][nj], al, bh[2 * nj], bh[2 * nj + 1]);
            }
        }
    }
}

__device__ __forceinline__ void zero_acc(float (&acc)[2][2][4]) {
#pragma unroll
    for (int i = 0; i < 2; i++)
#pragma unroll
        for (int j = 0; j < 2; j++)
#pragma unroll
            for (int q = 0; q < 4; q++) acc[i][j][q] = 0.0f;
}

__device__ __forceinline__ void store_part(const float (&acc)[2][2][4],
                                           int ks, int n0) {
    const int lane = threadIdx.x & 31, w = threadIdx.x >> 5;
    const int wm = (w & 1) * 32, wn = (w >> 1) * 16;
    const int gr = lane >> 2, tc = lane & 3;
    float* base = g_Cpart + ks * (BB * HH);
#pragma unroll
    for (int mi = 0; mi < 2; mi++)
#pragma unroll
        for (int nj = 0; nj < 2; nj++) {
            int r = wm + mi * 16 + gr;
            int c = n0 + wn + nj * 8 + tc * 2;
            *reinterpret_cast<float2*>(&base[r * HH + c]) =
                make_float2(acc[mi][nj][0], acc[mi][nj][1]);
            *reinterpret_cast<float2*>(&base[(r + 8) * HH + c]) =
                make_float2(acc[mi][nj][2], acc[mi][nj][3]);
        }
}

// grid barrier: release fence + arrive; last CTA bumps generation.
__device__ __forceinline__ void grid_barrier(unsigned& lgen) {
    __syncthreads();
    if (threadIdx.x == 0) {
        __threadfence();
        unsigned prev = atomicAdd(&g_bar_arrive, 1u);
        if (prev == GRIDP - 1) {
            g_bar_arrive = 0;
            __threadfence();
            g_bar_gen = lgen + 1;
        } else {
            while (g_bar_gen <= lgen) { }
        }
        lgen++;
        __threadfence();
    }
    __syncthreads();
}

// -------------------- kernel 1: prep (split + transpose) ------------------
__global__ void prep_kernel(const float* __restrict__ x,
                            const float* __restrict__ W0,
                            const float* __restrict__ W1) {
    int tid = blockIdx.x * blockDim.x + threadIdx.x;
    int stride = gridDim.x * blockDim.x;
    if (tid == 0) { g_bar_arrive = 0; g_bar_gen = 0; }

    for (int i = tid; i < BB * TT * DD; i += stride)
        split2(x[i], g_x_hi[i], g_x_lo[i]);
    for (int i = tid; i < HH * HH; i += stride) {
        int n = i >> 10, k = i & 1023;
        split2(W0[k * HH + n], g_W0h_hi[i], g_W0h_lo[i]);
    }
    for (int i = tid; i < HH * DD; i += stride) {
        int n = i >> 10, k = i & 1023;
        split2(W0[(HH + k) * HH + n], g_W0x_hi[i], g_W0x_lo[i]);
    }
    for (int i = tid; i < HH * KK1; i += stride) {
        int n = i >> 11, k = i & 2047;
        split2(W1[k * HH + n], g_W1_hi[i], g_W1_lo[i]);
    }
    bf16 z = __float2bfloat16(0.0f);
    for (int i = tid; i < BB * HH; i += stride) { g_A0_hi[i] = z; g_A0_lo[i] = z; }
    for (int i = tid; i < BB * KK1; i += stride) { g_A1_hi[i] = z; g_A1_lo[i] = z; }
}

// -------------------- kernel 2: U = x @ W0x + b0 ---------------------------
// 8192 CTAs; 16 consecutive bids share one m-tile so x stays L2-hot.
#define PRE_SMEM (4 * 64 * LDK0 * 2)
__global__ void __launch_bounds__(BLK) precompute_kernel(const float* __restrict__ b0) {
    extern __shared__ bf16 sm[];
    bf16* sA_hi = sm;
    bf16* sA_lo = sA_hi + 64 * LDK0;
    bf16* sW_hi = sA_lo + 64 * LDK0;
    bf16* sW_lo = sW_hi + 64 * LDK0;

    const int mtile = blockIdx.x >> 4;    // 512 m-tiles of 64 rows (b*T+t flat)
    const int ntile = blockIdx.x & 15;    // 16 n-tiles of 64 cols
    const int row0 = mtile * 64, n0 = ntile * 64;

    uint32_t uA_hi = s2u(sA_hi), uA_lo = s2u(sA_lo);
    uint32_t uW_hi = s2u(sW_hi), uW_lo = s2u(sW_lo);

    float acc[2][2][4];
    zero_acc(acc);

    for (int kc = 0; kc < 8; kc++) {
        if (kc) __syncthreads();
        stage<128, LDK0>(g_x_hi + row0 * DD + kc * 128, DD, sA_hi);
        stage<128, LDK0>(g_x_lo + row0 * DD + kc * 128, DD, sA_lo);
        stage<128, LDK0>(g_W0x_hi + n0 * DD + kc * 128, DD, sW_hi);
        stage<128, LDK0>(g_W0x_lo + n0 * DD + kc * 128, DD, sW_lo);
        __syncthreads();
        gemm_smem<LDK0>(uA_hi, uA_lo, uW_hi, uW_lo, 128, acc);
    }

    const int lane = threadIdx.x & 31, w = threadIdx.x >> 5;
    const int wm = (w & 1) * 32, wn = (w >> 1) * 16;
    const int gr = lane >> 2, tc = lane & 3;
#pragma unroll
    for (int mi = 0; mi < 2; mi++)
#pragma unroll
        for (int nj = 0; nj < 2; nj++) {
            int r = row0 + wm + mi * 16 + gr;
            int c = n0 + wn + nj * 8 + tc * 2;
            float bA = b0[c], bBv = b0[c + 1];
            g_U[r * HH + c]           = acc[mi][nj][0] + bA;
            g_U[r * HH + c + 1]       = acc[mi][nj][1] + bBv;
            g_U[(r + 8) * HH + c]     = acc[mi][nj][2] + bA;
            g_U[(r + 8) * HH + c + 1] = acc[mi][nj][3] + bBv;
        }
}

// -------------------- kernel 3: persistent recurrence ----------------------
// smem: W0h slice [64][LDK0] hi/lo + W1 slice [64][LDK1] hi/lo + A [64][LDK1] hi/lo
#define RNN_SMEM ((2 * 64 * LDK0 + 4 * 64 * LDK1) * 2)
__global__ void __launch_bounds__(BLK) rnn_kernel(const float* __restrict__ b1,
                                                  float* __restrict__ out) {
    extern __shared__ bf16 sm[];
    bf16* sW0_hi = sm;
    bf16* sW0_lo = sW0_hi + 64 * LDK0;
    bf16* sW1_hi = sW0_lo + 64 * LDK0;
    bf16* sW1_lo = sW1_hi + 64 * LDK1;
    bf16* sA_hi  = sW1_lo + 64 * LDK1;
    bf16* sA_lo  = sA_hi + 64 * LDK1;

    const int bid = blockIdx.x;
    const int ntile = bid & 15;      // 16 n-tiles of 64
    const int ks = bid >> 4;         // 8 k-splits
    const int n0 = ntile * 64;
    const int gtid = bid * BLK + threadIdx.x;

    // Preload this CTA's weight slices into smem ONCE (persist across t-loop;
    // smem is untouched by the barrier's L1 invalidations).
    stage<128, LDK0>(g_W0h_hi + n0 * HH + ks * 128, HH, sW0_hi);
    stage<128, LDK0>(g_W0h_lo + n0 * HH + ks * 128, HH, sW0_lo);
    stage<256, LDK1>(g_W1_hi + n0 * KK1 + ks * 256, KK1, sW1_hi);
    stage<256, LDK1>(g_W1_lo + n0 * KK1 + ks * 256, KK1, sW1_lo);

    uint32_t uW0_hi = s2u(sW0_hi), uW0_lo = s2u(sW0_lo);
    uint32_t uW1_hi = s2u(sW1_hi), uW1_lo = s2u(sW1_lo);
    uint32_t uA_hi = s2u(sA_hi), uA_lo = s2u(sA_lo);

    unsigned lgen = 0;
    if (threadIdx.x == 0) lgen = g_bar_gen;
    __syncthreads();

    for (int t = 0; t < TT; t++) {
        // ---- layer 0 GEMM: h0_prev @ W0h, K split 8 x 128 ----
        stage<128, LDK0>(g_A0_hi + ks * 128, HH, sA_hi);
        stage<128, LDK0>(g_A0_lo + ks * 128, HH, sA_lo);
        __syncthreads();
        {
            float acc[2][2][4];
            zero_acc(acc);
            gemm_smem<LDK0>(uA_hi, uA_lo, uW0_hi, uW0_lo, 128, acc);
            store_part(acc, ks, n0);
        }
        grid_barrier(lgen);

        // ---- reduce0 + tanh -> h0 (exactly one float2 per thread) ----
        {
            int idx = gtid;  // BB*HH/2 == GRIDP*BLK
            int e = idx * 2;
            int m = e >> 10, n = e & 1023;
            float2 u = *reinterpret_cast<const float2*>(&g_U[(m * TT + t) * HH + n]);
            float s0 = u.x, s1 = u.y;
#pragma unroll
            for (int p = 0; p < NSPLIT; p++) {
                float2 v = *reinterpret_cast<const float2*>(&g_Cpart[p * (BB * HH) + e]);
                s0 += v.x; s1 += v.y;
            }
            float h0a = tanhf(s0), h0b = tanhf(s1);
            __nv_bfloat162 hh, ll;
            split2(h0a, hh.x, ll.x);
            split2(h0b, hh.y, ll.y);
            *reinterpret_cast<__nv_bfloat162*>(&g_A1_hi[m * KK1 + HH + n]) = hh;
            *reinterpret_cast<__nv_bfloat162*>(&g_A1_lo[m * KK1 + HH + n]) = ll;
            *reinterpret_cast<__nv_bfloat162*>(&g_A0_hi[e]) = hh;
            *reinterpret_cast<__nv_bfloat162*>(&g_A0_lo[e]) = ll;
            if (t == TT - 1) {
                out[BB * TT * HH + m * (2 * HH) + n]     = h0a;  // h0_f
                out[BB * TT * HH + m * (2 * HH) + n + 1] = h0b;
            }
        }
        grid_barrier(lgen);

        // ---- layer 1 GEMM: [h1_prev | h0] @ W1, K split 8 x 256 ----
        stage<256, LDK1>(g_A1_hi + ks * 256, KK1, sA_hi);
        stage<256, LDK1>(g_A1_lo + ks * 256, KK1, sA_lo);
        __syncthreads();
        {
            float acc[2][2][4];
            zero_acc(acc);
            gemm_smem<LDK1>(uA_hi, uA_lo, uW1_hi, uW1_lo, 256, acc);
            store_part(acc, ks, n0);
        }
        grid_barrier(lgen);

        // ---- reduce1 + tanh -> h1; write outputs ----
        {
            int idx = gtid;
            int e = idx * 2;
            int m = e >> 10, n = e & 1023;
            float s0 = b1[n], s1 = b1[n + 1];
#pragma unroll
            for (int p = 0; p < NSPLIT; p++) {
                float2 v = *reinterpret_cast<const float2*>(&g_Cpart[p * (BB * HH) + e]);
                s0 += v.x; s1 += v.y;
            }
            float h1a = tanhf(s0), h1b = tanhf(s1);
            __nv_bfloat162 hh, ll;
            split2(h1a, hh.x, ll.x);
            split2(h1b, hh.y, ll.y);
            *reinterpret_cast<__nv_bfloat162*>(&g_A1_hi[m * KK1 + n]) = hh;
            *reinterpret_cast<__nv_bfloat162*>(&g_A1_lo[m * KK1 + n]) = ll;
            *reinterpret_cast<float2*>(&out[(m * TT + t) * HH + n]) =
                make_float2(h1a, h1b);
            if (t == TT - 1) {
                out[BB * TT * HH + m * (2 * HH) + HH + n]     = h1a;  // h1_f
                out[BB * TT * HH + m * (2 * HH) + HH + n + 1] = h1b;
            }
        }
        grid_barrier(lgen);
    }
}

// -------------------- launch ----------------------------------------------
extern "C" void kernel_launch(void* const* d_in, const int* in_sizes, int n_in,
                              void* d_out, int out_size) {
    const float* x = nullptr;
    const float* W[2] = {nullptr, nullptr};
    const float* bv[2] = {nullptr, nullptr};
    int nw = 0, nb = 0;
    for (int i = 0; i < n_in; i++) {
        if (in_sizes[i] == BB * TT * DD) x = (const float*)d_in[i];
        else if (in_sizes[i] == KK1 * HH) { if (nw < 2) W[nw++] = (const float*)d_in[i]; }
        else if (in_sizes[i] == HH)       { if (nb < 2) bv[nb++] = (const float*)d_in[i]; }
    }
    const float* W0 = W[0];
    const float* W1 = W[1];
    const float* b0 = bv[0];
    const float* b1 = bv[1];
    float* out = (float*)d_out;

    cudaFuncSetAttribute(precompute_kernel,
                         cudaFuncAttributeMaxDynamicSharedMemorySize, PRE_SMEM);
    cudaFuncSetAttribute(rnn_kernel,
                         cudaFuncAttributeMaxDynamicSharedMemorySize, RNN_SMEM);

    prep_kernel<<<2048, 256>>>(x, W0, W1);
    precompute_kernel<<<512 * 16, BLK, PRE_SMEM>>>(b0);
    rnn_kernel<<<GRIDP, BLK, RNN_SMEM>>>(b1, out);
}